// round 8
// baseline (speedup 1.0000x reference)
#include <cuda_runtime.h>
#include <cuda_bf16.h>
#include <cstdint>

// Folded table in GLOBAL memory (i-independent, built once by a pre-kernel):
//   rows   0..4  : C[c] = W[65] + W[131] + W[133+c]   (diff chain, HOT)
//   row    5     : W[132]                             (entity row)
//   rows   6..70 : A[r] = W[r] + W[131] + W[138]      (same chain, dres!=0)
//   rows  71..135: B[t] = W[32] + W[66+t] + W[138]    (same chain, dres==0)
//
// Phase B writes output via TMA bulk stores: stage 16 j-rows (8KB) in smem
// (STS.128, ~3x cheaper issue than STG.128), then ONE cp.async.bulk per chunk.
// Double-buffered; LSU store-issue bottleneck moves to the TMA engine.

#define TAB_ROWS 136
#define CHUNK_ROWS 16
#define CHUNK_BYTES (CHUNK_ROWS * 512)

__device__ float g_table[TAB_ROWS * 128];

__global__ void build_table(const float* __restrict__ W)
{
    const int idx = blockIdx.x * blockDim.x + threadIdx.x;
    if (idx >= TAB_ROWS * 128) return;
    const int r = idx >> 7;
    const int e = idx & 127;
    float v;
    if (r < 5) {
        v = W[65 * 128 + e] + W[131 * 128 + e] + W[(133 + r) * 128 + e];
    } else if (r == 5) {
        v = W[132 * 128 + e];
    } else if (r < 71) {
        v = W[(r - 6) * 128 + e] + W[131 * 128 + e] + W[138 * 128 + e];
    } else {
        v = W[32 * 128 + e] + W[(66 + (r - 71)) * 128 + e] + W[138 * 128 + e];
    }
    g_table[idx] = v;
}

__global__ void __launch_bounds__(256, 7)
rpe_main(const float* __restrict__ feats, float* __restrict__ out, int n)
{
    __shared__ int jidx[1024];
    __shared__ __align__(16) float4 stage[2][CHUNK_ROWS * 32];   // 2 x 8KB

    const int tid = threadIdx.x;
    const int i   = blockIdx.x;

    // ---- Phase A: per-j packed index (row | ent<<8) ----
    const float res_i  = feats[i * 10 + 0];
    const float tok_i  = feats[i * 10 + 1];
    const float asym_i = feats[i * 10 + 2];
    const float ent_i  = feats[i * 10 + 3];
    const float sym_i  = feats[i * 10 + 4];

    for (int j = tid; j < n; j += blockDim.x) {
        const float res_j  = feats[j * 10 + 0];
        const float tok_j  = feats[j * 10 + 1];
        const float asym_j = feats[j * 10 + 2];
        const float ent_j  = feats[j * 10 + 3];
        const float sym_j  = feats[j * 10 + 4];

        int row;
        if (asym_i == asym_j) {
            const int dres = (int)(res_i - res_j);
            if (dres != 0) {
                row = 6 + min(max(dres + 32, 0), 64);          // A table
            } else {
                const int dtok = (int)(tok_i - tok_j);
                row = 71 + min(max(dtok + 32, 0), 64);         // B table
            }
        } else {
            row = min(max((int)(sym_i - sym_j) + 2, 0), 4);    // C table (hot)
        }
        const int ent = (ent_i == ent_j) ? 1 : 0;
        jidx[j] = row | (ent << 8);
    }
    __syncthreads();

    // ---- Phase B: stage chunks in smem, TMA bulk-store to gmem ----
    const int e4  = tid & 31;                    // float4 lane within 128-dim row
    const int wid = tid >> 5;                    // 8 warps, 2 rows each per chunk
    const float4* __restrict__ T4 = (const float4*)g_table;

    const float4 went = __ldg(&T4[5 * 32 + e4]); // entity row in registers

    char* __restrict__ out_i = (char*)(out + ((size_t)i * (size_t)n) * 128);
    const int nchunks = n / CHUNK_ROWS;          // 64

    uint32_t st_addr[2];
    st_addr[0] = (uint32_t)__cvta_generic_to_shared(&stage[0][0]);
    st_addr[1] = (uint32_t)__cvta_generic_to_shared(&stage[1][0]);

    for (int c = 0; c < nchunks; c++) {
        const int buf = c & 1;
        if (c >= 2 && tid == 0) {
            // buffer c-2's bulk read must be done before we overwrite it
            asm volatile("cp.async.bulk.wait_group.read 1;" ::: "memory");
        }
        __syncthreads();

        #pragma unroll
        for (int u = 0; u < 2; u++) {
            const int r = wid * 2 + u;
            const int p = jidx[c * CHUNK_ROWS + r];
            float4 v = __ldg(&T4[(p & 255) * 32 + e4]);
            if (p >> 8) { v.x += went.x; v.y += went.y; v.z += went.z; v.w += went.w; }
            stage[buf][r * 32 + e4] = v;
        }
        __syncthreads();

        if (tid == 0) {
            asm volatile("fence.proxy.async.shared::cta;" ::: "memory");
            asm volatile(
                "cp.async.bulk.global.shared::cta.bulk_group [%0], [%1], %2;"
                :: "l"(out_i + (size_t)c * CHUNK_BYTES),
                   "r"(st_addr[buf]), "r"(CHUNK_BYTES)
                : "memory");
            asm volatile("cp.async.bulk.commit_group;" ::: "memory");
        }
    }
    if (tid == 0) {
        asm volatile("cp.async.bulk.wait_group 0;" ::: "memory");
    }
}

extern "C" void kernel_launch(void* const* d_in, const int* in_sizes, int n_in,
                              void* d_out, int out_size)
{
    const float* feats = (const float*)d_in[0];   // [1, n, 10] f32
    const float* W     = (const float*)d_in[1];   // [139, 128] f32
    float* out         = (float*)d_out;           // [1, n, n, 128] f32

    const int n = in_sizes[0] / 10;               // b == 1 (n == 1024)

    build_table<<<(TAB_ROWS * 128 + 255) / 256, 256>>>(W);
    rpe_main<<<n, 256>>>(feats, out, n);
}